// round 2
// baseline (speedup 1.0000x reference)
#include <cuda_runtime.h>
#include <math.h>

#define N_PTS 30000
#define M_AT  8000
#define D     16
#define KNN   16
#define NK    (N_PTS*KNN)
#define BN_EPS 1e-5
#define SLOPE 0.2f
#define CHUNK 2048

// ---- scratch (device globals: no runtime allocation allowed) ----
__device__ float4 g_atoms[M_AT];        // x,y,z, |y|^2
__device__ float  g_t[M_AT*D];          // transformed atom features
__device__ int    g_idx[NK];            // knn indices
__device__ float  g_invd[NK];           // 1/dist^2 features
__device__ float  g_h1[NK*D];           // leaky(conv1) pre-BN
__device__ float  g_h2[NK*D];           // leaky(conv2) pre-BN
__device__ float  g_fx1[N_PTS*D];       // pooled stage-1 output
__device__ double g_stats[4*D];         // sum1, sq1, sum2, sq2
__device__ float  g_A1[D], g_B1[D], g_A2[D], g_B2[D];  // BN affine folds

__device__ __forceinline__ float lrelu(float x){ return x > 0.f ? x : SLOPE*x; }

__global__ void k_init(){
  int i = threadIdx.x;
  if (i < 4*D) g_stats[i] = 0.0;
}

// ---- transform_types MLP (3x Linear(16,16)+leaky) + atom packing ----
__global__ void __launch_bounds__(256) k_prep(
    const float* __restrict__ atom_types, const float* __restrict__ atom_xyz,
    const float* __restrict__ Wt1, const float* __restrict__ bt1,
    const float* __restrict__ Wt2, const float* __restrict__ bt2,
    const float* __restrict__ Wt3, const float* __restrict__ bt3){
  __shared__ float sW[3][D][D];
  __shared__ float sb[3][D];
  __shared__ float s_row[D][D+1];
  int tid = threadIdx.x;
  sW[0][tid>>4][tid&15] = Wt1[tid];
  sW[1][tid>>4][tid&15] = Wt2[tid];
  sW[2][tid>>4][tid&15] = Wt3[tid];
  if (tid < D){ sb[0][tid]=bt1[tid]; sb[1][tid]=bt2[tid]; sb[2][tid]=bt3[tid]; }
  __syncthreads();
  int r = tid>>4, d = tid&15;
  int atom = blockIdx.x*16 + r;
  float v = atom_types[atom*D+d];
  #pragma unroll
  for (int L=0; L<3; L++){
    s_row[r][d] = v;
    __syncthreads();
    float acc = sb[L][d];
    #pragma unroll
    for (int i=0;i<D;i++) acc = fmaf(s_row[r][i], sW[L][i][d], acc);
    v = lrelu(acc);
    __syncthreads();
  }
  g_t[atom*D+d] = v;
  if (d == 0){
    float x = atom_xyz[atom*3+0], y = atom_xyz[atom*3+1], z = atom_xyz[atom*3+2];
    g_atoms[atom] = make_float4(x, y, z, x*x + y*y + z*z);
  }
}

// ---- brute-force kNN: per-thread point, shared-memory atom chunks ----
__global__ void __launch_bounds__(256) k_knn(const float* __restrict__ xyz){
  __shared__ float4 s_at[CHUNK];
  int pt = blockIdx.x*blockDim.x + threadIdx.x;
  bool act = pt < N_PTS;
  float px=0.f, py=0.f, pz=0.f, sx=0.f;
  if (act){
    px = xyz[pt*3+0]; py = xyz[pt*3+1]; pz = xyz[pt*3+2];
    sx = px*px + py*py + pz*pz;
  }
  float bd[KNN]; int bi[KNN];
  #pragma unroll
  for (int j=0;j<KNN;j++){ bd[j] = 3.4e38f; bi[j] = 0; }

  for (int c0 = 0; c0 < M_AT; c0 += CHUNK){
    int cn = min(CHUNK, M_AT - c0);
    __syncthreads();
    for (int i = threadIdx.x; i < cn; i += blockDim.x) s_at[i] = g_atoms[c0+i];
    __syncthreads();
    if (act){
      #pragma unroll 4
      for (int i=0; i<cn; i++){
        float4 a = s_at[i];
        float dot = px*a.x + py*a.y + pz*a.z;
        float d2  = (sx + a.w) - 2.f*dot;   // same expansion as reference
        if (d2 < bd[KNN-1]){                 // strict <: matches jax lower-index ties
          bd[KNN-1] = d2; bi[KNN-1] = c0 + i;
          #pragma unroll
          for (int j=KNN-1; j>0; j--){
            if (bd[j] < bd[j-1]){
              float td=bd[j]; bd[j]=bd[j-1]; bd[j-1]=td;
              int   ti=bi[j]; bi[j]=bi[j-1]; bi[j-1]=ti;
            }
          }
        }
      }
    }
  }
  if (act){
    #pragma unroll
    for (int j=0;j<KNN;j++){
      int a = bi[j];
      float4 av = g_atoms[a];
      float dx = px-av.x, dy = py-av.y, dz = pz-av.z;
      float dist = dx*dx + dy*dy + dz*dz;   // exact recompute (as in reference)
      g_idx [pt*KNN+j] = a;
      g_invd[pt*KNN+j] = 1.0f/dist;
    }
  }
}

// ---- conv1 + leaky + bn1 stats ----
__global__ void __launch_bounds__(256) k_conv1(const float* __restrict__ W1,
                                               const float* __restrict__ b1){
  __shared__ float sW[D+1][D];
  __shared__ float sb[D];
  __shared__ float s_f[D][D+1];
  int tid = threadIdx.x;
  for (int i=tid; i<(D+1)*D; i+=256) sW[i>>4][i&15] = W1[i];
  if (tid < D) sb[tid] = b1[tid];
  __syncthreads();
  int r = tid>>4, d = tid&15;
  float lsum = 0.f, lsq = 0.f;
  for (int g = blockIdx.x; g < N_PTS; g += gridDim.x){
    int row = g*KNN + r;
    int a = g_idx[row];
    s_f[r][d] = g_t[a*D+d];
    __syncthreads();
    float acc = sb[d];
    #pragma unroll
    for (int i=0;i<D;i++) acc = fmaf(s_f[r][i], sW[i][d], acc);
    acc = fmaf(g_invd[row], sW[D][d], acc);
    float h = lrelu(acc);
    g_h1[row*D+d] = h;
    lsum += h; lsq = fmaf(h, h, lsq);
    __syncthreads();
  }
  s_f[r][d] = lsum; __syncthreads();
  if (r == 0){
    float s = 0.f;
    #pragma unroll
    for (int j=0;j<D;j++) s += s_f[j][d];
    atomicAdd(&g_stats[d], (double)s);
  }
  __syncthreads();
  s_f[r][d] = lsq; __syncthreads();
  if (r == 0){
    float s = 0.f;
    #pragma unroll
    for (int j=0;j<D;j++) s += s_f[j][d];
    atomicAdd(&g_stats[D+d], (double)s);
  }
}

// ---- BN finalize: fold into affine A*x+B ----
__global__ void k_fin(const float* __restrict__ gma, const float* __restrict__ bet,
                      int stage){
  int d = threadIdx.x;
  if (d >= D) return;
  double s  = g_stats[stage*2*D + d];
  double sq = g_stats[stage*2*D + D + d];
  double mean = s / (double)NK;
  double var  = sq / (double)NK - mean*mean;
  float inv = (float)(1.0 / sqrt(var + BN_EPS));
  float Av = inv * gma[d];
  float Bv = bet[d] - (float)mean * Av;
  if (stage == 0){ g_A1[d]=Av; g_B1[d]=Bv; } else { g_A2[d]=Av; g_B2[d]=Bv; }
}

// ---- bn1 apply + K-sum pool + conv2 + leaky + bn2 stats ----
__global__ void __launch_bounds__(256) k_stage2(const float* __restrict__ W2,
                                                const float* __restrict__ b2){
  __shared__ float sW[D][D];
  __shared__ float sb[D], sA[D], sB[D];
  __shared__ float s_fx[D][D+1];
  int tid = threadIdx.x;
  sW[tid>>4][tid&15] = W2[tid];
  if (tid < D){ sb[tid]=b2[tid]; sA[tid]=g_A1[tid]; sB[tid]=g_B1[tid]; }
  __syncthreads();
  int k = tid>>4, d = tid&15;
  float lsum = 0.f, lsq = 0.f;
  for (int n = blockIdx.x; n < N_PTS; n += gridDim.x){
    int row = n*KNN + k;
    float h  = g_h1[row*D+d];
    float fx = fmaf(h, sA[d], sB[d]);
    s_fx[k][d] = fx;
    __syncthreads();
    if (k == 0){
      float s = 0.f;
      #pragma unroll
      for (int j=0;j<KNN;j++) s += s_fx[j][d];
      g_fx1[n*D+d] = s;
    }
    float acc = sb[d];
    #pragma unroll
    for (int i=0;i<D;i++) acc = fmaf(s_fx[k][i], sW[i][d], acc);
    float h2 = lrelu(acc);
    g_h2[row*D+d] = h2;
    lsum += h2; lsq = fmaf(h2, h2, lsq);
    __syncthreads();
  }
  s_fx[k][d] = lsum; __syncthreads();
  if (k == 0){
    float s=0.f;
    #pragma unroll
    for (int j=0;j<D;j++) s += s_fx[j][d];
    atomicAdd(&g_stats[2*D+d], (double)s);
  }
  __syncthreads();
  s_fx[k][d] = lsq; __syncthreads();
  if (k == 0){
    float s=0.f;
    #pragma unroll
    for (int j=0;j<D;j++) s += s_fx[j][d];
    atomicAdd(&g_stats[3*D+d], (double)s);
  }
}

// ---- bn2 apply + K-sum + concat + final Linear(32,16) ----
__global__ void __launch_bounds__(256) k_stage3(const float* __restrict__ W3,
                                                const float* __restrict__ b3,
                                                float* __restrict__ out){
  __shared__ float sW[2*D][D];
  __shared__ float sb[D], sA[D], sB[D];
  __shared__ float s_fx[D][D+1];
  __shared__ float s_cat[2*D];
  int tid = threadIdx.x;
  for (int i=tid; i<2*D*D; i+=256) sW[i>>4][i&15] = W3[i];
  if (tid < D){ sb[tid]=b3[tid]; sA[tid]=g_A2[tid]; sB[tid]=g_B2[tid]; }
  __syncthreads();
  int k = tid>>4, d = tid&15;
  for (int n = blockIdx.x; n < N_PTS; n += gridDim.x){
    int row = n*KNN + k;
    float h  = g_h2[row*D+d];
    float fx = fmaf(h, sA[d], sB[d]);
    s_fx[k][d] = fx;
    if (k == 1) s_cat[d] = g_fx1[n*D+d];
    __syncthreads();
    if (k == 0){
      float s = 0.f;
      #pragma unroll
      for (int j=0;j<KNN;j++) s += s_fx[j][d];
      s_cat[D+d] = s;
    }
    __syncthreads();
    if (tid < D){
      float acc = sb[tid];
      #pragma unroll
      for (int i=0;i<2*D;i++) acc = fmaf(s_cat[i], sW[i][tid], acc);
      out[n*D+tid] = acc;
    }
    __syncthreads();
  }
}

extern "C" void kernel_launch(void* const* d_in, const int* in_sizes, int n_in,
                              void* d_out, int out_size){
  const float* xyz        = (const float*)d_in[0];
  const float* atom_xyz   = (const float*)d_in[1];
  const float* atom_types = (const float*)d_in[2];
  const float* Wt1 = (const float*)d_in[3];  const float* bt1 = (const float*)d_in[4];
  const float* Wt2 = (const float*)d_in[5];  const float* bt2 = (const float*)d_in[6];
  const float* Wt3 = (const float*)d_in[7];  const float* bt3 = (const float*)d_in[8];
  const float* W1  = (const float*)d_in[9];  const float* b1  = (const float*)d_in[10];
  const float* W2  = (const float*)d_in[11]; const float* b2  = (const float*)d_in[12];
  const float* W3  = (const float*)d_in[13]; const float* b3  = (const float*)d_in[14];
  const float* g1  = (const float*)d_in[15]; const float* be1 = (const float*)d_in[16];
  const float* g2  = (const float*)d_in[17]; const float* be2 = (const float*)d_in[18];
  float* out = (float*)d_out;

  k_init  <<<1, 64>>>();
  k_prep  <<<M_AT/16, 256>>>(atom_types, atom_xyz, Wt1,bt1, Wt2,bt2, Wt3,bt3);
  k_knn   <<<(N_PTS+255)/256, 256>>>(xyz);
  k_conv1 <<<592, 256>>>(W1, b1);
  k_fin   <<<1, 16>>>(g1, be1, 0);
  k_stage2<<<592, 256>>>(W2, b2);
  k_fin   <<<1, 16>>>(g2, be2, 1);
  k_stage3<<<592, 256>>>(W3, b3, out);
}